// round 8
// baseline (speedup 1.0000x reference)
#include <cuda_runtime.h>
#include <cuda_bf16.h>
#include <math.h>
#include <cstdint>

#define B_SZ 512
#define K_SZ 32
#define D_SZ 768
#define N_SENSES 200000
#define NEG_INF -1e30f

#define WARPS_PER_CTA 8
#define CTA_THREADS (WARPS_PER_CTA * 32)
// 2 candidates per warp -> 16 warps per sample -> 2 CTAs per sample
#define GRID_CTAS (B_SZ * 2)   // 1024

// Global scratch. Counters use atomicInc wrap -> self-reset each full launch.
__device__ float    g_logits[B_SZ * K_SZ];
__device__ float    g_nll[B_SZ];
__device__ unsigned g_cnt[B_SZ];     // wraps at 15 (16 warp-arrivals per sample)
__device__ unsigned g_done = 0;      // wraps at B_SZ-1

__global__ __launch_bounds__(CTA_THREADS, 3)
void cbert_mlp_kernel(const float* __restrict__ reps,
                      const float* __restrict__ weight,
                      const float* __restrict__ bias,
                      const int* __restrict__ sense_ids,
                      const int* __restrict__ target_ids,
                      float* __restrict__ out, int out_size) {
    __shared__ __align__(16) float s_reps[D_SZ];   // 3 KB

    const int tid  = threadIdx.x;
    const int lane = tid & 31;
    const int warp = tid >> 5;

    const int b = blockIdx.x >> 1;                       // sample
    const int wslot = warp + WARPS_PER_CTA * (blockIdx.x & 1);  // 0..15
    const int k0 = wslot * 2;                            // candidates k0, k0+1

    // Stage reps[b] once per CTA (192 float4, 256 threads)
    {
        const float4* src = reinterpret_cast<const float4*>(reps + (size_t)b * D_SZ);
        float4* dst = reinterpret_cast<float4*>(s_reps);
        if (tid < D_SZ / 4) dst[tid] = src[tid];
    }

    // Warp-uniform candidate ids (8B aligned pair load)
    const int2 idp = *reinterpret_cast<const int2*>(&sense_ids[b * K_SZ + k0]);
    const int id0 = idp.x, id1 = idp.y;
    const bool v0 = (id0 >= 0 && id0 < N_SENSES);
    const bool v1 = (id1 >= 0 && id1 < N_SENSES);

    // Front-batch ALL 12 independent LDG.128 (interleaved across both rows).
    const float4* w0p = reinterpret_cast<const float4*>(weight + (size_t)(v0 ? id0 : 0) * D_SZ);
    const float4* w1p = reinterpret_cast<const float4*>(weight + (size_t)(v1 ? id1 : 0) * D_SZ);
    float4 w0[6], w1[6];
    #pragma unroll
    for (int j = 0; j < 6; ++j) {
        const int i = lane + 32 * j;
        if (v0) w0[j] = w0p[i];
        if (v1) w1[j] = w1p[i];
    }
    // Bias gathers overlap with in-flight row loads.
    float bias0 = v0 ? __ldg(&bias[id0]) : 0.f;
    float bias1 = v1 ? __ldg(&bias[id1]) : 0.f;

    __syncthreads();   // s_reps ready

    float acc0 = 0.f, acc1 = 0.f;
    const float4* r4 = reinterpret_cast<const float4*>(s_reps);
    #pragma unroll
    for (int j = 0; j < 6; ++j) {
        const float4 r = r4[lane + 32 * j];
        if (v0) {
            acc0 = fmaf(w0[j].x, r.x, acc0);
            acc0 = fmaf(w0[j].y, r.y, acc0);
            acc0 = fmaf(w0[j].z, r.z, acc0);
            acc0 = fmaf(w0[j].w, r.w, acc0);
        }
        if (v1) {
            acc1 = fmaf(w1[j].x, r.x, acc1);
            acc1 = fmaf(w1[j].y, r.y, acc1);
            acc1 = fmaf(w1[j].z, r.z, acc1);
            acc1 = fmaf(w1[j].w, r.w, acc1);
        }
    }
    #pragma unroll
    for (int off = 16; off > 0; off >>= 1) {
        acc0 += __shfl_down_sync(0xFFFFFFFFu, acc0, off);
        acc1 += __shfl_down_sync(0xFFFFFFFFu, acc1, off);
    }

    // ---- Publish logits; count warp arrivals for sample b ----
    unsigned old = 0;
    if (lane == 0) {
        __stcg(&g_logits[b * K_SZ + k0],     v0 ? acc0 + bias0 : NEG_INF);
        __stcg(&g_logits[b * K_SZ + k0 + 1], v1 ? acc1 + bias1 : NEG_INF);
        __threadfence();
        old = atomicInc(&g_cnt[b], 15u);     // wraps to 0 after 16 arrivals
    }
    old = __shfl_sync(0xFFFFFFFFu, old, 0);
    if (old != 15u) return;

    // ---- Phase 2: last warp of sample b -> 32-wide masked softmax ----
    __threadfence();
    float v = __ldcg(&g_logits[b * K_SZ + lane]);

    float mval = v; int midx = lane;
    #pragma unroll
    for (int off = 16; off > 0; off >>= 1) {
        float ov = __shfl_down_sync(0xFFFFFFFFu, mval, off);
        int   oi = __shfl_down_sync(0xFFFFFFFFu, midx, off);
        if (ov > mval || (ov == mval && oi < midx)) { mval = ov; midx = oi; }
    }
    mval = __shfl_sync(0xFFFFFFFFu, mval, 0);
    midx = __shfl_sync(0xFFFFFFFFu, midx, 0);

    float e = expf(v - mval);
    #pragma unroll
    for (int off = 16; off > 0; off >>= 1)
        e += __shfl_down_sync(0xFFFFFFFFu, e, off);
    float sumexp = __shfl_sync(0xFFFFFFFFu, e, 0);

    const int tgt = target_ids[b];
    float tlogit = __shfl_sync(0xFFFFFFFFu, v, tgt & 31);

    unsigned done2 = 0;
    if (lane == 0) {
        float nll = -(tlogit - mval - logf(sumexp));
        __stcg(&g_nll[b], nll);
        if (1 + b < out_size) out[1 + b] = (midx == tgt) ? 1.0f : 0.0f;
        __threadfence();
        done2 = atomicInc(&g_done, B_SZ - 1);
    }
    done2 = __shfl_sync(0xFFFFFFFFu, done2, 0);
    if (done2 != B_SZ - 1) return;

    // ---- Phase 3: deterministic fixed-order mean of 512 NLLs ----
    __threadfence();
    float acc = 0.f;
    #pragma unroll
    for (int i = 0; i < B_SZ / 32; ++i)
        acc += __ldcg(&g_nll[lane + 32 * i]);
    #pragma unroll
    for (int off = 16; off > 0; off >>= 1)
        acc += __shfl_down_sync(0xFFFFFFFFu, acc, off);
    if (lane == 0 && out_size > 0) out[0] = acc / (float)B_SZ;
}

extern "C" void kernel_launch(void* const* d_in, const int* in_sizes, int n_in,
                              void* d_out, int out_size) {
    const float* reps = (const float*)d_in[0];
    const float* weight = (const float*)d_in[1];
    const float* bias = (const float*)d_in[2];
    const int* sense_ids = (const int*)d_in[3];
    const int* target_ids = (const int*)d_in[4];
    float* out = (float*)d_out;

    cbert_mlp_kernel<<<GRID_CTAS, CTA_THREADS>>>(reps, weight, bias,
                                                 sense_ids, target_ids,
                                                 out, out_size);
}

// round 9
// speedup vs baseline: 1.1065x; 1.1065x over previous
#include <cuda_runtime.h>
#include <cuda_bf16.h>
#include <math.h>
#include <cstdint>

#define B_SZ 512
#define K_SZ 32
#define D_SZ 768
#define N_SENSES 200000
#define NEG_INF -1e30f

#define WARPS_PER_CTA 8             // 8 candidates of the SAME sample per CTA
#define CTA_THREADS (WARPS_PER_CTA * 32)
#define GRID_CTAS ((B_SZ * K_SZ) / WARPS_PER_CTA)   // 2048

// Global scratch. Counters use atomicInc wrap -> self-reset each full launch.
__device__ float    g_logits[B_SZ * K_SZ];
__device__ float    g_nll[B_SZ];
__device__ unsigned g_cnt[B_SZ];     // wraps at K_SZ-1 (32 warp arrivals)
__device__ unsigned g_done = 0;      // wraps at B_SZ-1

__device__ __forceinline__ uint32_t smem_u32(const void* p) {
    return (uint32_t)__cvta_generic_to_shared(p);
}

__global__ __launch_bounds__(CTA_THREADS, 4)
void cbert_dualpath_kernel(const float* __restrict__ reps,
                           const float* __restrict__ weight,
                           const float* __restrict__ bias,
                           const int* __restrict__ sense_ids,
                           const int* __restrict__ target_ids,
                           float* __restrict__ out, int out_size) {
    __shared__ __align__(16) float s_reps[D_SZ];            // 3 KB
    __shared__ __align__(16) float s_w[WARPS_PER_CTA / 2][D_SZ];  // 12 KB (odd warps)

    const int tid  = threadIdx.x;
    const int lane = tid & 31;
    const int warp = tid >> 5;
    const int gwarp = blockIdx.x * WARPS_PER_CTA + warp;
    const int b = gwarp >> 5;          // same b for the whole CTA
    const int k = gwarp & 31;

    const int id = __ldg(&sense_ids[b * K_SZ + k]);
    const bool valid = (id >= 0 && id < N_SENSES);
    const bool lpath = ((warp & 1) == 0);   // even warps: LDG path; odd: cp.async

    // ---- Issue phase (both memory paths in flight simultaneously) ----
    // Cooperative reps staging (192 float4 over 256 threads)
    {
        const float4* src = reinterpret_cast<const float4*>(reps + (size_t)b * D_SZ);
        float4* dst = reinterpret_cast<float4*>(s_reps);
        if (tid < D_SZ / 4) dst[tid] = src[tid];
    }

    float4 wreg[6];                 // LDG-path row (registers)
    const int slot = warp >> 1;     // cp.async-path smem slot for odd warps

    if (lpath) {
        if (valid) {
            const float4* wp = reinterpret_cast<const float4*>(weight + (size_t)id * D_SZ);
            #pragma unroll
            for (int j = 0; j < 6; ++j)       // 6 independent LDG.128, front-batched
                wreg[j] = wp[lane + 32 * j];
        }
    } else {
        if (valid) {
            const char* src = reinterpret_cast<const char*>(weight + (size_t)id * D_SZ) + lane * 16;
            uint32_t dst = smem_u32(&s_w[slot][0]) + lane * 16;
            #pragma unroll
            for (int j = 0; j < 6; ++j)       // register-free async copies
                asm volatile("cp.async.cg.shared.global [%0], [%1], 16;"
                             :: "r"(dst + j * 512), "l"(src + j * 512) : "memory");
        }
        asm volatile("cp.async.commit_group;" ::: "memory");
    }
    float bval = valid ? __ldg(&bias[id]) : 0.f;   // overlaps with row traffic

    __syncthreads();   // s_reps visible

    // ---- Dot product ----
    float logit = NEG_INF;
    const float4* r4 = reinterpret_cast<const float4*>(s_reps);
    if (valid) {
        float acc = 0.f;
        if (lpath) {
            #pragma unroll
            for (int j = 0; j < 6; ++j) {
                const float4 r = r4[lane + 32 * j];
                acc = fmaf(wreg[j].x, r.x, acc);
                acc = fmaf(wreg[j].y, r.y, acc);
                acc = fmaf(wreg[j].z, r.z, acc);
                acc = fmaf(wreg[j].w, r.w, acc);
            }
        } else {
            asm volatile("cp.async.wait_group 0;" ::: "memory");
            __syncwarp();
            const float4* w4 = reinterpret_cast<const float4*>(&s_w[slot][0]);
            #pragma unroll
            for (int j = 0; j < 6; ++j) {
                const int i = lane + 32 * j;
                const float4 w = w4[i];
                const float4 r = r4[i];
                acc = fmaf(w.x, r.x, acc);
                acc = fmaf(w.y, r.y, acc);
                acc = fmaf(w.z, r.z, acc);
                acc = fmaf(w.w, r.w, acc);
            }
        }
        #pragma unroll
        for (int off = 16; off > 0; off >>= 1)
            acc += __shfl_down_sync(0xFFFFFFFFu, acc, off);
        if (lane == 0) logit = acc + bval;
    }

    // ---- Phase 2 trigger: publish logit, count arrivals for sample b ----
    unsigned old = 0;
    if (lane == 0) {
        __stcg(&g_logits[b * K_SZ + k], logit);
        __threadfence();
        old = atomicInc(&g_cnt[b], K_SZ - 1);
    }
    old = __shfl_sync(0xFFFFFFFFu, old, 0);
    if (old != K_SZ - 1) return;

    // ---- Phase 2: last warp for sample b -> 32-wide masked softmax ----
    __threadfence();
    float v = __ldcg(&g_logits[b * K_SZ + lane]);

    float mval = v; int midx = lane;
    #pragma unroll
    for (int off = 16; off > 0; off >>= 1) {
        float ov = __shfl_down_sync(0xFFFFFFFFu, mval, off);
        int   oi = __shfl_down_sync(0xFFFFFFFFu, midx, off);
        if (ov > mval || (ov == mval && oi < midx)) { mval = ov; midx = oi; }
    }
    mval = __shfl_sync(0xFFFFFFFFu, mval, 0);
    midx = __shfl_sync(0xFFFFFFFFu, midx, 0);

    float e = expf(v - mval);
    #pragma unroll
    for (int off = 16; off > 0; off >>= 1)
        e += __shfl_down_sync(0xFFFFFFFFu, e, off);
    float sumexp = __shfl_sync(0xFFFFFFFFu, e, 0);

    const int tgt = target_ids[b];
    float tlogit = __shfl_sync(0xFFFFFFFFu, v, tgt & 31);

    unsigned done2 = 0;
    if (lane == 0) {
        float nll = -(tlogit - mval - logf(sumexp));
        __stcg(&g_nll[b], nll);
        if (1 + b < out_size) out[1 + b] = (midx == tgt) ? 1.0f : 0.0f;
        __threadfence();
        done2 = atomicInc(&g_done, B_SZ - 1);
    }
    done2 = __shfl_sync(0xFFFFFFFFu, done2, 0);
    if (done2 != B_SZ - 1) return;

    // ---- Phase 3: deterministic fixed-order mean of 512 NLLs ----
    __threadfence();
    float acc = 0.f;
    #pragma unroll
    for (int i = 0; i < B_SZ / 32; ++i)
        acc += __ldcg(&g_nll[lane + 32 * i]);
    #pragma unroll
    for (int off = 16; off > 0; off >>= 1)
        acc += __shfl_down_sync(0xFFFFFFFFu, acc, off);
    if (lane == 0 && out_size > 0) out[0] = acc / (float)B_SZ;
}

extern "C" void kernel_launch(void* const* d_in, const int* in_sizes, int n_in,
                              void* d_out, int out_size) {
    const float* reps = (const float*)d_in[0];
    const float* weight = (const float*)d_in[1];
    const float* bias = (const float*)d_in[2];
    const int* sense_ids = (const int*)d_in[3];
    const int* target_ids = (const int*)d_in[4];
    float* out = (float*)d_out;

    cbert_dualpath_kernel<<<GRID_CTAS, CTA_THREADS>>>(reps, weight, bias,
                                                      sense_ids, target_ids,
                                                      out, out_size);
}